// round 6
// baseline (speedup 1.0000x reference)
#include <cuda_runtime.h>

// Problem constants (fixed shapes)
#define NSZ   1536
#define NNSZ  (NSZ * NSZ)          // 2,359,296  (== 9216 * 256 exactly)

// ---------------------------------------------------------------------------
// Scratch (device globals -- allocation-free rule)
// z planes stored SoA: g_z[c * NNSZ + p]. 16 planes (max width). 151 MB BSS.
// Reused in place across layers (widths shrink 16->16->8->8; each thread
// reads all its inputs at a unique p before writing the same p).
// ---------------------------------------------------------------------------
__device__ __align__(16) float  g_z[16 * NNSZ];
__device__ double g_sumP[8][16];     // sliced partial sums  (8 copies to spread atomics)
__device__ double g_sqP[8][16];      // sliced partial sums of squares
__device__ float  g_scaleA[4][16];   // per-layer BN affine: y = z*scale + shift
__device__ float  g_shiftA[4][16];

// ---------------------------------------------------------------------------
// K0: zero stats partials (first pass only; finalize kernels re-zero after use)
// ---------------------------------------------------------------------------
__global__ void k_zero() {
    int t = threadIdx.x;
    if (t < 128) {
        ((double*)g_sumP)[t] = 0.0;
        ((double*)g_sqP)[t]  = 0.0;
    }
}

// ---------------------------------------------------------------------------
// K1: adj generation + layer-1 matmul + bias, store z1 (16 planes), accumulate
// stats.  Block = 256 threads covering an (8 i) x (128 j) position tile.
// Thread t: tj = t&127 (its j), tig = t>>7 (warp-uniform) selects 4 of 8 i's.
// x_j tile (128 rows) staged in smem with +4 float pad => conflict-free LDS128.
// ---------------------------------------------------------------------------
__global__ void __launch_bounds__(256) k_l1(const float* __restrict__ x,
                                            const float* __restrict__ W1,
                                            const float* __restrict__ b1) {
    __shared__ __align__(16) float sXj[128][68];   // pad 4 => row stride 272B (16B-aligned)
    __shared__ __align__(16) float sXi[8][64];
    __shared__ __align__(16) float sW[16][64];     // W1[o][c] row-major
    __shared__ float sB[16];
    __shared__ float sRed[8][32];

    const int t  = threadIdx.x;
    const int j0 = blockIdx.x * 128;
    const int i0 = blockIdx.y * 8;

    const float4* x4 = (const float4*)x;
    // fill x_j tile: 128 rows x 16 float4
    for (int l = t; l < 128 * 16; l += 256) {
        int r = l >> 4, c4 = l & 15;
        *((float4*)&sXj[r][c4 * 4]) = x4[(j0 + r) * 16 + c4];
    }
    // fill x_i tile: 8 rows x 16 float4
    if (t < 8 * 16) {
        int r = t >> 4, c4 = t & 15;
        *((float4*)&sXi[r][c4 * 4]) = x4[(i0 + r) * 16 + c4];
    }
    // fill W1: exactly 256 float4
    ((float4*)sW)[t] = ((const float4*)W1)[t];
    if (t < 16) sB[t] = b1[t];
    __syncthreads();

    const int tj  = t & 127;
    const int tig = t >> 7;            // warp-uniform

    float fsum[16], fsq[16];
#pragma unroll
    for (int o = 0; o < 16; o++) { fsum[o] = 0.f; fsq[o] = 0.f; }

    for (int ii = tig; ii < 8; ii += 2) {
        float acc[16];
#pragma unroll
        for (int o = 0; o < 16; o++) acc[o] = 0.f;

#pragma unroll
        for (int c4 = 0; c4 < 16; c4++) {
            float4 a = *((const float4*)&sXi[ii][c4 * 4]);   // warp-uniform broadcast
            float4 b = *((const float4*)&sXj[tj][c4 * 4]);   // conflict-free
            float dx = fabsf(a.x - b.x);
            float dy = fabsf(a.y - b.y);
            float dz = fabsf(a.z - b.z);
            float dw = fabsf(a.w - b.w);
#pragma unroll
            for (int o = 0; o < 16; o++) {
                float4 w = *((const float4*)&sW[o][c4 * 4]); // broadcast
                acc[o] += dx * w.x;
                acc[o] += dy * w.y;
                acc[o] += dz * w.z;
                acc[o] += dw * w.w;
            }
        }

        const int p = (i0 + ii) * NSZ + j0 + tj;             // coalesced over tj
#pragma unroll
        for (int o = 0; o < 16; o++) {
            float z = acc[o] + sB[o];
            g_z[o * NNSZ + p] = z;
            fsum[o] += z;
            fsq[o]  += z * z;
        }
    }

    // --- block stats reduction: warp shfl -> smem -> 8-way add -> sliced atomics
#pragma unroll
    for (int o = 0; o < 16; o++) {
#pragma unroll
        for (int s = 16; s > 0; s >>= 1) {
            fsum[o] += __shfl_xor_sync(0xffffffffu, fsum[o], s);
            fsq[o]  += __shfl_xor_sync(0xffffffffu, fsq[o],  s);
        }
    }
    const int w = t >> 5, lane = t & 31;
    if (lane == 0) {
#pragma unroll
        for (int o = 0; o < 16; o++) { sRed[w][o] = fsum[o]; sRed[w][16 + o] = fsq[o]; }
    }
    __syncthreads();
    if (t < 32) {
        float v = 0.f;
#pragma unroll
        for (int b = 0; b < 8; b++) v += sRed[b][t];
        int slice = (blockIdx.y * 12 + blockIdx.x) & 7;
        if (t < 16) atomicAdd(&g_sumP[slice][t], (double)v);
        else        atomicAdd(&g_sqP[slice][t - 16], (double)v);
    }
}

// ---------------------------------------------------------------------------
// Finalize BN affine for `layer` (H channels) from accumulated stats; then
// zero the partials for the next stats pass.  1 block, 32 threads.
// ---------------------------------------------------------------------------
__global__ void k_fin(const float* __restrict__ gamma, const float* __restrict__ beta,
                      int layer, int H) {
    __shared__ double ss[16], qq[16];
    int t = threadIdx.x;
    if (t < 16) {
        double s = 0.0, q = 0.0;
        for (int b = 0; b < 8; b++) { s += g_sumP[b][t]; q += g_sqP[b][t]; }
        ss[t] = s; qq[t] = q;
    }
    __syncthreads();
    for (int l = t; l < 128; l += 32) {
        ((double*)g_sumP)[l] = 0.0;
        ((double*)g_sqP)[l]  = 0.0;
    }
    if (t < H) {
        double mean = ss[t] / (double)NNSZ;
        double var  = qq[t] / (double)NNSZ - mean * mean;   // biased variance (torch/jnp)
        double inv  = 1.0 / sqrt(var + 1e-5);
        float  sc   = (float)((double)gamma[t] * inv);
        g_scaleA[layer][t] = sc;
        g_shiftA[layer][t] = beta[t] - (float)mean * sc;
    }
}

// ---------------------------------------------------------------------------
// Middle layer: read CI planes, apply BN(prev)+leaky, matmul W[CO][CI]+bias,
// write CO planes, accumulate stats for this layer.  grid 9216 x 256 == NNSZ.
// ---------------------------------------------------------------------------
template <int CI, int CO>
__global__ void __launch_bounds__(256) k_mid(const float* __restrict__ Wm,
                                             const float* __restrict__ bias,
                                             int layerPrev) {
    __shared__ float sW[CO * CI];
    __shared__ float sS[CI], sH[CI], sB2[CO];
    __shared__ float sRed[8][32];
    int t = threadIdx.x;
    for (int l = t; l < CO * CI; l += 256) sW[l] = Wm[l];
    if (t < CI) { sS[t] = g_scaleA[layerPrev][t]; sH[t] = g_shiftA[layerPrev][t]; }
    if (t < CO) sB2[t] = bias[t];
    __syncthreads();

    int p = blockIdx.x * 256 + t;        // exact: 9216*256 == NNSZ
    float h[CI];
#pragma unroll
    for (int c = 0; c < CI; c++) {
        float z = g_z[c * NNSZ + p];
        z = z * sS[c] + sH[c];
        h[c] = (z >= 0.f) ? z : 0.01f * z;
    }
    float acc[CO], sq[CO];
#pragma unroll
    for (int o = 0; o < CO; o++) {
        float a = sB2[o];
#pragma unroll
        for (int c = 0; c < CI; c++) a += sW[o * CI + c] * h[c];
        g_z[o * NNSZ + p] = a;
        acc[o] = a; sq[o] = a * a;
    }
#pragma unroll
    for (int o = 0; o < CO; o++) {
#pragma unroll
        for (int s = 16; s > 0; s >>= 1) {
            acc[o] += __shfl_xor_sync(0xffffffffu, acc[o], s);
            sq[o]  += __shfl_xor_sync(0xffffffffu, sq[o],  s);
        }
    }
    int w = t >> 5, lane = t & 31;
    if (lane == 0) {
#pragma unroll
        for (int o = 0; o < CO; o++) { sRed[w][o] = acc[o]; sRed[w][CO + o] = sq[o]; }
    }
    __syncthreads();
    if (t < 2 * CO) {
        float v = 0.f;
#pragma unroll
        for (int b = 0; b < 8; b++) v += sRed[b][t];
        int slice = blockIdx.x & 7;
        if (t < CO) atomicAdd(&g_sumP[slice][t], (double)v);
        else        atomicAdd(&g_sqP[slice][t - CO], (double)v);
    }
}

// ---------------------------------------------------------------------------
// Output: BN4 + leaky + dot with W5[8] + b5 -> out[p] (fp32)
// ---------------------------------------------------------------------------
__global__ void __launch_bounds__(256) k_out(const float* __restrict__ W5,
                                             const float* __restrict__ b5,
                                             float* __restrict__ out) {
    __shared__ float sS[8], sH[8], sW[8];
    __shared__ float sb;
    int t = threadIdx.x;
    if (t < 8) { sS[t] = g_scaleA[3][t]; sH[t] = g_shiftA[3][t]; sW[t] = W5[t]; }
    if (t == 0) sb = b5[0];
    __syncthreads();
    int p = blockIdx.x * 256 + t;
    float a = sb;
#pragma unroll
    for (int c = 0; c < 8; c++) {
        float z = g_z[c * NNSZ + p] * sS[c] + sH[c];
        float h = (z >= 0.f) ? z : 0.01f * z;
        a += sW[c] * h;
    }
    out[p] = a;
}

// ---------------------------------------------------------------------------
// Launch: 10 kernels, all graph-capturable, no allocations, no syncs.
// Input order (metadata): x, W1,b1,g1,be1, W2,b2,g2,be2, W3,b3,g3,be3,
//                         W4,b4,g4,be4, W5,b5
// ---------------------------------------------------------------------------
extern "C" void kernel_launch(void* const* d_in, const int* in_sizes, int n_in,
                              void* d_out, int out_size) {
    (void)in_sizes; (void)n_in; (void)out_size;
    const float* x   = (const float*)d_in[0];
    const float* W1  = (const float*)d_in[1];
    const float* b1  = (const float*)d_in[2];
    const float* g1  = (const float*)d_in[3];
    const float* be1 = (const float*)d_in[4];
    const float* W2  = (const float*)d_in[5];
    const float* b2  = (const float*)d_in[6];
    const float* g2  = (const float*)d_in[7];
    const float* be2 = (const float*)d_in[8];
    const float* W3  = (const float*)d_in[9];
    const float* b3  = (const float*)d_in[10];
    const float* g3  = (const float*)d_in[11];
    const float* be3 = (const float*)d_in[12];
    const float* W4  = (const float*)d_in[13];
    const float* b4  = (const float*)d_in[14];
    const float* g4  = (const float*)d_in[15];
    const float* be4 = (const float*)d_in[16];
    const float* W5  = (const float*)d_in[17];
    const float* b5  = (const float*)d_in[18];
    float* out = (float*)d_out;

    const int nblk = NNSZ / 256;   // 9216

    k_zero<<<1, 128>>>();
    k_l1<<<dim3(NSZ / 128, NSZ / 8), 256>>>(x, W1, b1);     // z1 + stats1
    k_fin<<<1, 32>>>(g1, be1, 0, 16);
    k_mid<16, 16><<<nblk, 256>>>(W2, b2, 0);                // z2 + stats2
    k_fin<<<1, 32>>>(g2, be2, 1, 16);
    k_mid<16, 8><<<nblk, 256>>>(W3, b3, 1);                 // z3 + stats3
    k_fin<<<1, 32>>>(g3, be3, 2, 8);
    k_mid<8, 8><<<nblk, 256>>>(W4, b4, 2);                  // z4 + stats4
    k_fin<<<1, 32>>>(g4, be4, 3, 8);
    k_out<<<nblk, 256>>>(W5, b5, out);
}

// round 8
// speedup vs baseline: 2.2712x; 2.2712x over previous
#include <cuda_runtime.h>

#define NSZ   1536
#define NNSZ  (NSZ * NSZ)          // 2,359,296  (== 9216*256 == 1152*2048)

// ---------------------------------------------------------------------------
// Scratch (device globals -- allocation-free rule). 151 MB BSS.
// z planes SoA: g_z[c * NNSZ + p]; reused in place (widths 16->16->8->8,
// each thread reads all inputs at its p before writing the same p).
// ---------------------------------------------------------------------------
__device__ __align__(16) float  g_z[16 * NNSZ];
__device__ double g_sumP[8][16];     // sliced partials (8 copies spread atomics)
__device__ double g_sqP[8][16];
__device__ float  g_scaleA[4][16];   // BN affine: y = z*scale + shift
__device__ float  g_shiftA[4][16];

// ---- packed f32x2 helpers (sm_103a) ---------------------------------------
__device__ __forceinline__ unsigned long long f2fma(unsigned long long a,
                                                    unsigned long long b,
                                                    unsigned long long c) {
    unsigned long long d;
    asm("fma.rn.f32x2 %0, %1, %2, %3;" : "=l"(d) : "l"(a), "l"(b), "l"(c));
    return d;
}
__device__ __forceinline__ unsigned long long f2add(unsigned long long a,
                                                    unsigned long long b) {
    unsigned long long d;
    asm("add.rn.f32x2 %0, %1, %2;" : "=l"(d) : "l"(a), "l"(b));
    return d;
}
__device__ __forceinline__ unsigned long long f2dup(float x) {
    unsigned long long d;
    unsigned u = __float_as_uint(x);
    asm("mov.b64 %0, {%1, %1};" : "=l"(d) : "r"(u));
    return d;
}
__device__ __forceinline__ float f2lo(unsigned long long a) {
    return __uint_as_float((unsigned)(a & 0xFFFFFFFFull));
}
__device__ __forceinline__ float f2hi(unsigned long long a) {
    return __uint_as_float((unsigned)(a >> 32));
}

// ---------------------------------------------------------------------------
// K0: zero stats partials
// ---------------------------------------------------------------------------
__global__ void k_zero() {
    int t = threadIdx.x;
    if (t < 128) {
        ((double*)g_sumP)[t] = 0.0;
        ((double*)g_sqP)[t]  = 0.0;
    }
}

// ---------------------------------------------------------------------------
// K1: adj + layer-1 matmul + bias -> z1 (16 planes) + stats.
// Block = 256 threads over an (8 i) x (128 j) tile; thread = 1 i-row x 4 j
// positions, packed as two f32x2 pairs. x_j tile stored TRANSPOSED+NEGATED
// (sNXjT[c][jj]) so diff = add.f32x2; W stored channel-major DUPLICATED
// (sWd[c][2o],[2o+1] = W[o][c]) so the inner loop has zero pack movs.
// ---------------------------------------------------------------------------
__global__ void __launch_bounds__(256, 2) k_l1(const float* __restrict__ x,
                                               const float* __restrict__ W1,
                                               const float* __restrict__ b1) {
    __shared__ __align__(16) float sNXjT[64][132];  // 33.8KB, rows 528B (16B-mult)
    __shared__ __align__(16) float sXi[8][64];      // 2KB
    __shared__ __align__(16) float sWd[64][32];     // 8KB  dup'd weight pairs
    __shared__ float sB[16];
    __shared__ float sRed[8][32];

    const int t  = threadIdx.x;
    const int j0 = blockIdx.x * 128;
    const int i0 = blockIdx.y * 8;

    // fill x_j transposed + negated (coalesced global reads)
    for (int idx = t; idx < 128 * 64; idx += 256) {
        int jj = idx >> 6, c = idx & 63;
        sNXjT[c][jj] = -x[(j0 + jj) * 64 + c];
    }
    // fill x_i
    for (int idx = t; idx < 8 * 64; idx += 256) {
        int r = idx >> 6, c = idx & 63;
        sXi[r][c] = x[(i0 + r) * 64 + c];
    }
    // fill duplicated weights: sWd[c][2o]=sWd[c][2o+1]=W1[o][c]
    for (int idx = t; idx < 64 * 16; idx += 256) {
        int c = idx >> 4, o = idx & 15;
        float w = W1[o * 64 + c];
        sWd[c][2 * o]     = w;
        sWd[c][2 * o + 1] = w;
    }
    if (t < 16) sB[t] = b1[t];
    __syncthreads();

    const int jq   = t & 31;    // lane = j-quad index (4 consecutive j)
    const int irow = t >> 5;    // warp-uniform i row within tile

    unsigned long long acc0[16], acc1[16];  // pair (j,j+1), pair (j+2,j+3)
#pragma unroll
    for (int o = 0; o < 16; o++) { acc0[o] = 0ull; acc1[o] = 0ull; }

    const unsigned long long ABSM = 0x7FFFFFFF7FFFFFFFull;

#pragma unroll 8
    for (int c = 0; c < 64; c++) {
        unsigned long long xid = f2dup(sXi[irow][c]);            // bcast LDS + mov
        ulonglong2 nx = *(const ulonglong2*)&sNXjT[c][4 * jq];   // LDS.128, conflict-free
        unsigned long long d0 = f2add(xid, nx.x) & ABSM;         // |xi - xj| packed
        unsigned long long d1 = f2add(xid, nx.y) & ABSM;
        const ulonglong2* wrow = (const ulonglong2*)&sWd[c][0];
#pragma unroll
        for (int o2 = 0; o2 < 8; o2++) {
            ulonglong2 wp = wrow[o2];                            // bcast LDS.128
            acc0[2 * o2]     = f2fma(d0, wp.x, acc0[2 * o2]);
            acc1[2 * o2]     = f2fma(d1, wp.x, acc1[2 * o2]);
            acc0[2 * o2 + 1] = f2fma(d0, wp.y, acc0[2 * o2 + 1]);
            acc1[2 * o2 + 1] = f2fma(d1, wp.y, acc1[2 * o2 + 1]);
        }
    }

    // epilogue: bias, vectorized store, local stats
    const int p = (i0 + irow) * NSZ + j0 + 4 * jq;   // 16B-aligned (j mult of 4)
    float lsum[16], lsq[16];
#pragma unroll
    for (int o = 0; o < 16; o++) {
        float b = sB[o];
        float z0 = f2lo(acc0[o]) + b;
        float z1 = f2hi(acc0[o]) + b;
        float z2 = f2lo(acc1[o]) + b;
        float z3 = f2hi(acc1[o]) + b;
        float4 zz = make_float4(z0, z1, z2, z3);
        *(float4*)&g_z[o * NNSZ + p] = zz;           // coalesced STG.128 over jq
        lsum[o] = z0 + z1 + z2 + z3;
        lsq[o]  = z0 * z0 + z1 * z1 + z2 * z2 + z3 * z3;
    }

    // warp shfl -> smem -> 8-way add -> sliced atomics (amortized over 4 pos)
#pragma unroll
    for (int o = 0; o < 16; o++) {
#pragma unroll
        for (int s = 16; s > 0; s >>= 1) {
            lsum[o] += __shfl_xor_sync(0xffffffffu, lsum[o], s);
            lsq[o]  += __shfl_xor_sync(0xffffffffu, lsq[o],  s);
        }
    }
    const int w = t >> 5, lane = t & 31;
    if (lane == 0) {
#pragma unroll
        for (int o = 0; o < 16; o++) { sRed[w][o] = lsum[o]; sRed[w][16 + o] = lsq[o]; }
    }
    __syncthreads();
    if (t < 32) {
        float v = 0.f;
#pragma unroll
        for (int b = 0; b < 8; b++) v += sRed[b][t];
        int slice = (blockIdx.y * 12 + blockIdx.x) & 7;
        if (t < 16) atomicAdd(&g_sumP[slice][t], (double)v);
        else        atomicAdd(&g_sqP[slice][t - 16], (double)v);
    }
}

// ---------------------------------------------------------------------------
// Finalize BN affine; re-zero partials.  1 block, 32 threads.
// ---------------------------------------------------------------------------
__global__ void k_fin(const float* __restrict__ gamma, const float* __restrict__ beta,
                      int layer, int H) {
    __shared__ double ss[16], qq[16];
    int t = threadIdx.x;
    if (t < 16) {
        double s = 0.0, q = 0.0;
        for (int b = 0; b < 8; b++) { s += g_sumP[b][t]; q += g_sqP[b][t]; }
        ss[t] = s; qq[t] = q;
    }
    __syncthreads();
    for (int l = t; l < 128; l += 32) {
        ((double*)g_sumP)[l] = 0.0;
        ((double*)g_sqP)[l]  = 0.0;
    }
    if (t < H) {
        double mean = ss[t] / (double)NNSZ;
        double var  = qq[t] / (double)NNSZ - mean * mean;   // biased variance
        double inv  = 1.0 / sqrt(var + 1e-5);
        float  sc   = (float)((double)gamma[t] * inv);
        g_scaleA[layer][t] = sc;
        g_shiftA[layer][t] = beta[t] - (float)mean * sc;
    }
}

// ---------------------------------------------------------------------------
// Middle layer: BN(prev)+leaky on CI planes, matmul W[CO][CI]+bias, write CO
// planes, stats for this layer.  ITER=8 positions/thread amortizes the SHFL
// reduction (was 160 shfl per single position => ~40us of MIO in R6).
// grid 1152 x 256 x 8 == NNSZ.
// ---------------------------------------------------------------------------
template <int CI, int CO>
__global__ void __launch_bounds__(256) k_mid(const float* __restrict__ Wm,
                                             const float* __restrict__ bias,
                                             int layerPrev) {
    __shared__ float sW[CO * CI];
    __shared__ float sS[CI], sH[CI], sB2[CO];
    __shared__ float sRed[8][32];
    int t = threadIdx.x;
    for (int l = t; l < CO * CI; l += 256) sW[l] = Wm[l];
    if (t < CI) { sS[t] = g_scaleA[layerPrev][t]; sH[t] = g_shiftA[layerPrev][t]; }
    if (t < CO) sB2[t] = bias[t];
    __syncthreads();

    float fsum[CO], fsq[CO];
#pragma unroll
    for (int o = 0; o < CO; o++) { fsum[o] = 0.f; fsq[o] = 0.f; }

    const int base = blockIdx.x * 2048 + t;
#pragma unroll
    for (int it = 0; it < 8; it++) {
        int p = base + it * 256;
        float h[CI];
#pragma unroll
        for (int c = 0; c < CI; c++) {
            float z = g_z[c * NNSZ + p];
            z = z * sS[c] + sH[c];
            h[c] = (z >= 0.f) ? z : 0.01f * z;
        }
#pragma unroll
        for (int o = 0; o < CO; o++) {
            float a = sB2[o];
#pragma unroll
            for (int c = 0; c < CI; c++) a += sW[o * CI + c] * h[c];
            g_z[o * NNSZ + p] = a;
            fsum[o] += a;
            fsq[o]  += a * a;
        }
    }

#pragma unroll
    for (int o = 0; o < CO; o++) {
#pragma unroll
        for (int s = 16; s > 0; s >>= 1) {
            fsum[o] += __shfl_xor_sync(0xffffffffu, fsum[o], s);
            fsq[o]  += __shfl_xor_sync(0xffffffffu, fsq[o],  s);
        }
    }
    int w = t >> 5, lane = t & 31;
    if (lane == 0) {
#pragma unroll
        for (int o = 0; o < CO; o++) { sRed[w][o] = fsum[o]; sRed[w][CO + o] = fsq[o]; }
    }
    __syncthreads();
    if (t < 2 * CO) {
        float v = 0.f;
#pragma unroll
        for (int b = 0; b < 8; b++) v += sRed[b][t];
        int slice = blockIdx.x & 7;
        if (t < CO) atomicAdd(&g_sumP[slice][t], (double)v);
        else        atomicAdd(&g_sqP[slice][t - CO], (double)v);
    }
}

// ---------------------------------------------------------------------------
// Output: BN4 + leaky + dot with W5[8] + b5.  8 positions/thread.
// ---------------------------------------------------------------------------
__global__ void __launch_bounds__(256) k_out(const float* __restrict__ W5,
                                             const float* __restrict__ b5,
                                             float* __restrict__ out) {
    __shared__ float sS[8], sH[8], sW[8];
    __shared__ float sb;
    int t = threadIdx.x;
    if (t < 8) { sS[t] = g_scaleA[3][t]; sH[t] = g_shiftA[3][t]; sW[t] = W5[t]; }
    if (t == 0) sb = b5[0];
    __syncthreads();
    const int base = blockIdx.x * 2048 + t;
#pragma unroll
    for (int it = 0; it < 8; it++) {
        int p = base + it * 256;
        float a = sb;
#pragma unroll
        for (int c = 0; c < 8; c++) {
            float z = g_z[c * NNSZ + p] * sS[c] + sH[c];
            float h = (z >= 0.f) ? z : 0.01f * z;
            a += sW[c] * h;
        }
        out[p] = a;
    }
}

// ---------------------------------------------------------------------------
// Launch: 10 kernels, graph-capturable, allocation-free, no syncs.
// ---------------------------------------------------------------------------
extern "C" void kernel_launch(void* const* d_in, const int* in_sizes, int n_in,
                              void* d_out, int out_size) {
    (void)in_sizes; (void)n_in; (void)out_size;
    const float* x   = (const float*)d_in[0];
    const float* W1  = (const float*)d_in[1];
    const float* b1  = (const float*)d_in[2];
    const float* g1  = (const float*)d_in[3];
    const float* be1 = (const float*)d_in[4];
    const float* W2  = (const float*)d_in[5];
    const float* b2  = (const float*)d_in[6];
    const float* g2  = (const float*)d_in[7];
    const float* be2 = (const float*)d_in[8];
    const float* W3  = (const float*)d_in[9];
    const float* b3  = (const float*)d_in[10];
    const float* g3  = (const float*)d_in[11];
    const float* be3 = (const float*)d_in[12];
    const float* W4  = (const float*)d_in[13];
    const float* b4  = (const float*)d_in[14];
    const float* g4  = (const float*)d_in[15];
    const float* be4 = (const float*)d_in[16];
    const float* W5  = (const float*)d_in[17];
    const float* b5  = (const float*)d_in[18];
    float* out = (float*)d_out;

    const int nblk = NNSZ / 2048;   // 1152

    k_zero<<<1, 128>>>();
    k_l1<<<dim3(NSZ / 128, NSZ / 8), 256>>>(x, W1, b1);     // z1 + stats1
    k_fin<<<1, 32>>>(g1, be1, 0, 16);
    k_mid<16, 16><<<nblk, 256>>>(W2, b2, 0);                // z2 + stats2
    k_fin<<<1, 32>>>(g2, be2, 1, 16);
    k_mid<16, 8><<<nblk, 256>>>(W3, b3, 1);                 // z3 + stats3
    k_fin<<<1, 32>>>(g3, be3, 2, 8);
    k_mid<8, 8><<<nblk, 256>>>(W4, b4, 2);                  // z4 + stats4
    k_fin<<<1, 32>>>(g4, be4, 3, 8);
    k_out<<<nblk, 256>>>(W5, b5, out);
}

// round 9
// speedup vs baseline: 2.3194x; 1.0212x over previous
#include <cuda_runtime.h>

#define NSZ   1536
#define NNSZ  (NSZ * NSZ)          // 2,359,296  (== 576*4096)

// ---------------------------------------------------------------------------
// Scratch (device globals -- allocation-free rule). 151 MB BSS.
// z planes SoA: g_z[c * NNSZ + p]; reused in place (widths 16->16->8->8,
// each thread reads all inputs at its positions before writing the same ones).
// ---------------------------------------------------------------------------
__device__ __align__(16) float  g_z[16 * NNSZ];
__device__ double g_sumP[8][16];     // sliced partials (8 copies spread atomics)
__device__ double g_sqP[8][16];
__device__ float  g_scaleA[4][16];   // BN affine: y = z*scale + shift
__device__ float  g_shiftA[4][16];

// ---- packed f32x2 helpers (sm_103a) ---------------------------------------
__device__ __forceinline__ unsigned long long f2fma(unsigned long long a,
                                                    unsigned long long b,
                                                    unsigned long long c) {
    unsigned long long d;
    asm("fma.rn.f32x2 %0, %1, %2, %3;" : "=l"(d) : "l"(a), "l"(b), "l"(c));
    return d;
}
__device__ __forceinline__ unsigned long long f2add(unsigned long long a,
                                                    unsigned long long b) {
    unsigned long long d;
    asm("add.rn.f32x2 %0, %1, %2;" : "=l"(d) : "l"(a), "l"(b));
    return d;
}
__device__ __forceinline__ unsigned long long f2dup(float x) {
    unsigned long long d;
    unsigned u = __float_as_uint(x);
    asm("mov.b64 %0, {%1, %1};" : "=l"(d) : "r"(u));
    return d;
}
__device__ __forceinline__ float f2lo(unsigned long long a) {
    return __uint_as_float((unsigned)(a & 0xFFFFFFFFull));
}
__device__ __forceinline__ float f2hi(unsigned long long a) {
    return __uint_as_float((unsigned)(a >> 32));
}

// ---------------------------------------------------------------------------
// K0: zero stats partials
// ---------------------------------------------------------------------------
__global__ void k_zero() {
    int t = threadIdx.x;
    if (t < 128) {
        ((double*)g_sumP)[t] = 0.0;
        ((double*)g_sqP)[t]  = 0.0;
    }
}

// ---------------------------------------------------------------------------
// K1: adj + layer-1 matmul + bias -> z1 (16 planes) + stats.
// (unchanged from R8 -- measured ~120us; f32x2 packed math, 4 j-pos/thread)
// ---------------------------------------------------------------------------
__global__ void __launch_bounds__(256, 2) k_l1(const float* __restrict__ x,
                                               const float* __restrict__ W1,
                                               const float* __restrict__ b1) {
    __shared__ __align__(16) float sNXjT[64][132];  // 33.8KB, rows 528B
    __shared__ __align__(16) float sXi[8][64];      // 2KB
    __shared__ __align__(16) float sWd[64][32];     // 8KB dup'd weight pairs
    __shared__ float sB[16];
    __shared__ float sRed[8][32];

    const int t  = threadIdx.x;
    const int j0 = blockIdx.x * 128;
    const int i0 = blockIdx.y * 8;

    for (int idx = t; idx < 128 * 64; idx += 256) {
        int jj = idx >> 6, c = idx & 63;
        sNXjT[c][jj] = -x[(j0 + jj) * 64 + c];
    }
    for (int idx = t; idx < 8 * 64; idx += 256) {
        int r = idx >> 6, c = idx & 63;
        sXi[r][c] = x[(i0 + r) * 64 + c];
    }
    for (int idx = t; idx < 64 * 16; idx += 256) {
        int c = idx >> 4, o = idx & 15;
        float w = W1[o * 64 + c];
        sWd[c][2 * o]     = w;
        sWd[c][2 * o + 1] = w;
    }
    if (t < 16) sB[t] = b1[t];
    __syncthreads();

    const int jq   = t & 31;
    const int irow = t >> 5;

    unsigned long long acc0[16], acc1[16];
#pragma unroll
    for (int o = 0; o < 16; o++) { acc0[o] = 0ull; acc1[o] = 0ull; }

    const unsigned long long ABSM = 0x7FFFFFFF7FFFFFFFull;

#pragma unroll 8
    for (int c = 0; c < 64; c++) {
        unsigned long long xid = f2dup(sXi[irow][c]);
        ulonglong2 nx = *(const ulonglong2*)&sNXjT[c][4 * jq];
        unsigned long long d0 = f2add(xid, nx.x) & ABSM;
        unsigned long long d1 = f2add(xid, nx.y) & ABSM;
        const ulonglong2* wrow = (const ulonglong2*)&sWd[c][0];
#pragma unroll
        for (int o2 = 0; o2 < 8; o2++) {
            ulonglong2 wp = wrow[o2];
            acc0[2 * o2]     = f2fma(d0, wp.x, acc0[2 * o2]);
            acc1[2 * o2]     = f2fma(d1, wp.x, acc1[2 * o2]);
            acc0[2 * o2 + 1] = f2fma(d0, wp.y, acc0[2 * o2 + 1]);
            acc1[2 * o2 + 1] = f2fma(d1, wp.y, acc1[2 * o2 + 1]);
        }
    }

    const int p = (i0 + irow) * NSZ + j0 + 4 * jq;
    float lsum[16], lsq[16];
#pragma unroll
    for (int o = 0; o < 16; o++) {
        float b = sB[o];
        float z0 = f2lo(acc0[o]) + b;
        float z1 = f2hi(acc0[o]) + b;
        float z2 = f2lo(acc1[o]) + b;
        float z3 = f2hi(acc1[o]) + b;
        float4 zz = make_float4(z0, z1, z2, z3);
        *(float4*)&g_z[o * NNSZ + p] = zz;
        lsum[o] = (z0 + z1) + (z2 + z3);
        lsq[o]  = (z0 * z0 + z1 * z1) + (z2 * z2 + z3 * z3);
    }

#pragma unroll
    for (int o = 0; o < 16; o++) {
#pragma unroll
        for (int s = 16; s > 0; s >>= 1) {
            lsum[o] += __shfl_xor_sync(0xffffffffu, lsum[o], s);
            lsq[o]  += __shfl_xor_sync(0xffffffffu, lsq[o],  s);
        }
    }
    const int w = t >> 5, lane = t & 31;
    if (lane == 0) {
#pragma unroll
        for (int o = 0; o < 16; o++) { sRed[w][o] = lsum[o]; sRed[w][16 + o] = lsq[o]; }
    }
    __syncthreads();
    if (t < 32) {
        float v = 0.f;
#pragma unroll
        for (int b = 0; b < 8; b++) v += sRed[b][t];
        int slice = (blockIdx.y * 12 + blockIdx.x) & 7;
        if (t < 16) atomicAdd(&g_sumP[slice][t], (double)v);
        else        atomicAdd(&g_sqP[slice][t - 16], (double)v);
    }
}

// ---------------------------------------------------------------------------
// Finalize BN affine; re-zero partials.  1 block, 32 threads.
// ---------------------------------------------------------------------------
__global__ void k_fin(const float* __restrict__ gamma, const float* __restrict__ beta,
                      int layer, int H) {
    __shared__ double ss[16], qq[16];
    int t = threadIdx.x;
    if (t < 16) {
        double s = 0.0, q = 0.0;
        for (int b = 0; b < 8; b++) { s += g_sumP[b][t]; q += g_sqP[b][t]; }
        ss[t] = s; qq[t] = q;
    }
    __syncthreads();
    for (int l = t; l < 128; l += 32) {
        ((double*)g_sumP)[l] = 0.0;
        ((double*)g_sqP)[l]  = 0.0;
    }
    if (t < H) {
        double mean = ss[t] / (double)NNSZ;
        double var  = qq[t] / (double)NNSZ - mean * mean;   // biased variance
        double inv  = 1.0 / sqrt(var + 1e-5);
        float  sc   = (float)((double)gamma[t] * inv);
        g_scaleA[layer][t] = sc;
        g_shiftA[layer][t] = beta[t] - (float)mean * sc;
    }
}

// ---------------------------------------------------------------------------
// Middle layer: BN(prev)+leaky on CI planes, matmul W[CO][CI]+bias, write CO
// planes, stats.  float4 = 4 consecutive positions per thread per iteration;
// NITER=4 iterations with `#pragma unroll 1` (CRITICAL: the R8 8x-unrolled
// loop made ptxas batch 128 loads -> reg clamp to 32 -> spills -> 4.6GB of
// local-memory traffic, 782us).  grid 576 x 256thr x 4pos x 4iter == NNSZ.
// ---------------------------------------------------------------------------
template <int CI, int CO>
__global__ void __launch_bounds__(256) k_mid(const float* __restrict__ Wm,
                                             const float* __restrict__ bias,
                                             int layerPrev) {
    __shared__ float sW[CO * CI];
    __shared__ float sS[CI], sH[CI], sB2[CO];
    __shared__ float sRed[8][32];
    int t = threadIdx.x;
    for (int l = t; l < CO * CI; l += 256) sW[l] = Wm[l];
    if (t < CI) { sS[t] = g_scaleA[layerPrev][t]; sH[t] = g_shiftA[layerPrev][t]; }
    if (t < CO) sB2[t] = bias[t];
    __syncthreads();

    float fsum[CO], fsq[CO];
#pragma unroll
    for (int o = 0; o < CO; o++) { fsum[o] = 0.f; fsq[o] = 0.f; }

    const int base = blockIdx.x * 4096 + t * 4;
#pragma unroll 1
    for (int it = 0; it < 4; it++) {
        const int p = base + it * 1024;
        float4 h4[CI];
#pragma unroll
        for (int c = 0; c < CI; c++) {
            float4 z = *(const float4*)&g_z[c * NNSZ + p];
            float sc = sS[c], sh = sH[c];
            z.x = z.x * sc + sh; z.x = (z.x >= 0.f) ? z.x : 0.01f * z.x;
            z.y = z.y * sc + sh; z.y = (z.y >= 0.f) ? z.y : 0.01f * z.y;
            z.z = z.z * sc + sh; z.z = (z.z >= 0.f) ? z.z : 0.01f * z.z;
            z.w = z.w * sc + sh; z.w = (z.w >= 0.f) ? z.w : 0.01f * z.w;
            h4[c] = z;
        }
#pragma unroll
        for (int o = 0; o < CO; o++) {
            float b = sB2[o];
            float4 a = make_float4(b, b, b, b);
#pragma unroll
            for (int c = 0; c < CI; c++) {
                float w = sW[o * CI + c];
                a.x += w * h4[c].x;
                a.y += w * h4[c].y;
                a.z += w * h4[c].z;
                a.w += w * h4[c].w;
            }
            *(float4*)&g_z[o * NNSZ + p] = a;
            fsum[o] += (a.x + a.y) + (a.z + a.w);
            fsq[o]  += (a.x * a.x + a.y * a.y) + (a.z * a.z + a.w * a.w);
        }
    }

#pragma unroll
    for (int o = 0; o < CO; o++) {
#pragma unroll
        for (int s = 16; s > 0; s >>= 1) {
            fsum[o] += __shfl_xor_sync(0xffffffffu, fsum[o], s);
            fsq[o]  += __shfl_xor_sync(0xffffffffu, fsq[o],  s);
        }
    }
    int w = t >> 5, lane = t & 31;
    if (lane == 0) {
#pragma unroll
        for (int o = 0; o < CO; o++) { sRed[w][o] = fsum[o]; sRed[w][CO + o] = fsq[o]; }
    }
    __syncthreads();
    if (t < 2 * CO) {
        float v = 0.f;
#pragma unroll
        for (int b = 0; b < 8; b++) v += sRed[b][t];
        int slice = blockIdx.x & 7;
        if (t < CO) atomicAdd(&g_sumP[slice][t], (double)v);
        else        atomicAdd(&g_sqP[slice][t - CO], (double)v);
    }
}

// ---------------------------------------------------------------------------
// Output: BN4 + leaky + dot with W5[8] + b5.  float4 x 4 iters, grid 576.
// ---------------------------------------------------------------------------
__global__ void __launch_bounds__(256) k_out(const float* __restrict__ W5,
                                             const float* __restrict__ b5,
                                             float* __restrict__ out) {
    __shared__ float sS[8], sH[8], sW[8];
    __shared__ float sb;
    int t = threadIdx.x;
    if (t < 8) { sS[t] = g_scaleA[3][t]; sH[t] = g_shiftA[3][t]; sW[t] = W5[t]; }
    if (t == 0) sb = b5[0];
    __syncthreads();
    const int base = blockIdx.x * 4096 + t * 4;
#pragma unroll 1
    for (int it = 0; it < 4; it++) {
        const int p = base + it * 1024;
        float4 a = make_float4(sb, sb, sb, sb);
#pragma unroll
        for (int c = 0; c < 8; c++) {
            float4 z = *(const float4*)&g_z[c * NNSZ + p];
            float sc = sS[c], sh = sH[c], w = sW[c];
            float h;
            h = z.x * sc + sh; h = (h >= 0.f) ? h : 0.01f * h; a.x += w * h;
            h = z.y * sc + sh; h = (h >= 0.f) ? h : 0.01f * h; a.y += w * h;
            h = z.z * sc + sh; h = (h >= 0.f) ? h : 0.01f * h; a.z += w * h;
            h = z.w * sc + sh; h = (h >= 0.f) ? h : 0.01f * h; a.w += w * h;
        }
        *(float4*)&out[p] = a;
    }
}

// ---------------------------------------------------------------------------
// Launch: 10 kernels, graph-capturable, allocation-free, no syncs.
// ---------------------------------------------------------------------------
extern "C" void kernel_launch(void* const* d_in, const int* in_sizes, int n_in,
                              void* d_out, int out_size) {
    (void)in_sizes; (void)n_in; (void)out_size;
    const float* x   = (const float*)d_in[0];
    const float* W1  = (const float*)d_in[1];
    const float* b1  = (const float*)d_in[2];
    const float* g1  = (const float*)d_in[3];
    const float* be1 = (const float*)d_in[4];
    const float* W2  = (const float*)d_in[5];
    const float* b2  = (const float*)d_in[6];
    const float* g2  = (const float*)d_in[7];
    const float* be2 = (const float*)d_in[8];
    const float* W3  = (const float*)d_in[9];
    const float* b3  = (const float*)d_in[10];
    const float* g3  = (const float*)d_in[11];
    const float* be3 = (const float*)d_in[12];
    const float* W4  = (const float*)d_in[13];
    const float* b4  = (const float*)d_in[14];
    const float* g4  = (const float*)d_in[15];
    const float* be4 = (const float*)d_in[16];
    const float* W5  = (const float*)d_in[17];
    const float* b5  = (const float*)d_in[18];
    float* out = (float*)d_out;

    const int nblk = NNSZ / 4096;   // 576

    k_zero<<<1, 128>>>();
    k_l1<<<dim3(NSZ / 128, NSZ / 8), 256>>>(x, W1, b1);     // z1 + stats1
    k_fin<<<1, 32>>>(g1, be1, 0, 16);
    k_mid<16, 16><<<nblk, 256>>>(W2, b2, 0);                // z2 + stats2
    k_fin<<<1, 32>>>(g2, be2, 1, 16);
    k_mid<16, 8><<<nblk, 256>>>(W3, b3, 1);                 // z3 + stats3
    k_fin<<<1, 32>>>(g3, be3, 2, 8);
    k_mid<8, 8><<<nblk, 256>>>(W4, b4, 2);                  // z4 + stats4
    k_fin<<<1, 32>>>(g4, be4, 3, 8);
    k_out<<<nblk, 256>>>(W5, b5, out);
}

// round 10
// speedup vs baseline: 5.3258x; 2.2962x over previous
#include <cuda_runtime.h>

#define NSZ   1536
#define NNSZ  (NSZ * NSZ)          // 2,359,296  (== 1152*2048)

// ---------------------------------------------------------------------------
// Scratch (device globals -- allocation-free rule). 151 MB BSS.
// z planes SoA: g_z[c * NNSZ + p]; reused in place (widths 16->16->8->8,
// each thread reads all inputs at its position before writing the same one).
// ---------------------------------------------------------------------------
__device__ __align__(16) float  g_z[16 * NNSZ];
__device__ double g_sumP[8][16];     // sliced partials (8 copies spread atomics)
__device__ double g_sqP[8][16];
__device__ float  g_scaleA[4][16];   // BN affine: y = z*scale + shift
__device__ float  g_shiftA[4][16];

// ---- packed f32x2 helpers (sm_103a) ---------------------------------------
__device__ __forceinline__ unsigned long long f2fma(unsigned long long a,
                                                    unsigned long long b,
                                                    unsigned long long c) {
    unsigned long long d;
    asm("fma.rn.f32x2 %0, %1, %2, %3;" : "=l"(d) : "l"(a), "l"(b), "l"(c));
    return d;
}
__device__ __forceinline__ unsigned long long f2add(unsigned long long a,
                                                    unsigned long long b) {
    unsigned long long d;
    asm("add.rn.f32x2 %0, %1, %2;" : "=l"(d) : "l"(a), "l"(b));
    return d;
}
__device__ __forceinline__ unsigned long long f2dup(float x) {
    unsigned long long d;
    unsigned u = __float_as_uint(x);
    asm("mov.b64 %0, {%1, %1};" : "=l"(d) : "r"(u));
    return d;
}
__device__ __forceinline__ float f2lo(unsigned long long a) {
    return __uint_as_float((unsigned)(a & 0xFFFFFFFFull));
}
__device__ __forceinline__ float f2hi(unsigned long long a) {
    return __uint_as_float((unsigned)(a >> 32));
}

// ---------------------------------------------------------------------------
// K0: zero stats partials
// ---------------------------------------------------------------------------
__global__ void k_zero() {
    int t = threadIdx.x;
    if (t < 128) {
        ((double*)g_sumP)[t] = 0.0;
        ((double*)g_sqP)[t]  = 0.0;
    }
}

// ---------------------------------------------------------------------------
// K1: adj + layer-1 matmul + bias -> z1 (16 planes) + stats.
// (unchanged since R8 -- inferred ~120us; f32x2 packed math, 4 j-pos/thread)
// ---------------------------------------------------------------------------
__global__ void __launch_bounds__(256, 2) k_l1(const float* __restrict__ x,
                                               const float* __restrict__ W1,
                                               const float* __restrict__ b1) {
    __shared__ __align__(16) float sNXjT[64][132];  // 33.8KB, rows 528B
    __shared__ __align__(16) float sXi[8][64];      // 2KB
    __shared__ __align__(16) float sWd[64][32];     // 8KB dup'd weight pairs
    __shared__ float sB[16];
    __shared__ float sRed[8][32];

    const int t  = threadIdx.x;
    const int j0 = blockIdx.x * 128;
    const int i0 = blockIdx.y * 8;

    for (int idx = t; idx < 128 * 64; idx += 256) {
        int jj = idx >> 6, c = idx & 63;
        sNXjT[c][jj] = -x[(j0 + jj) * 64 + c];
    }
    for (int idx = t; idx < 8 * 64; idx += 256) {
        int r = idx >> 6, c = idx & 63;
        sXi[r][c] = x[(i0 + r) * 64 + c];
    }
    for (int idx = t; idx < 64 * 16; idx += 256) {
        int c = idx >> 4, o = idx & 15;
        float w = W1[o * 64 + c];
        sWd[c][2 * o]     = w;
        sWd[c][2 * o + 1] = w;
    }
    if (t < 16) sB[t] = b1[t];
    __syncthreads();

    const int jq   = t & 31;
    const int irow = t >> 5;

    unsigned long long acc0[16], acc1[16];
#pragma unroll
    for (int o = 0; o < 16; o++) { acc0[o] = 0ull; acc1[o] = 0ull; }

    const unsigned long long ABSM = 0x7FFFFFFF7FFFFFFFull;

#pragma unroll 8
    for (int c = 0; c < 64; c++) {
        unsigned long long xid = f2dup(sXi[irow][c]);
        ulonglong2 nx = *(const ulonglong2*)&sNXjT[c][4 * jq];
        unsigned long long d0 = f2add(xid, nx.x) & ABSM;
        unsigned long long d1 = f2add(xid, nx.y) & ABSM;
        const ulonglong2* wrow = (const ulonglong2*)&sWd[c][0];
#pragma unroll
        for (int o2 = 0; o2 < 8; o2++) {
            ulonglong2 wp = wrow[o2];
            acc0[2 * o2]     = f2fma(d0, wp.x, acc0[2 * o2]);
            acc1[2 * o2]     = f2fma(d1, wp.x, acc1[2 * o2]);
            acc0[2 * o2 + 1] = f2fma(d0, wp.y, acc0[2 * o2 + 1]);
            acc1[2 * o2 + 1] = f2fma(d1, wp.y, acc1[2 * o2 + 1]);
        }
    }

    const int p = (i0 + irow) * NSZ + j0 + 4 * jq;
    float lsum[16], lsq[16];
#pragma unroll
    for (int o = 0; o < 16; o++) {
        float b = sB[o];
        float z0 = f2lo(acc0[o]) + b;
        float z1 = f2hi(acc0[o]) + b;
        float z2 = f2lo(acc1[o]) + b;
        float z3 = f2hi(acc1[o]) + b;
        float4 zz = make_float4(z0, z1, z2, z3);
        *(float4*)&g_z[o * NNSZ + p] = zz;
        lsum[o] = (z0 + z1) + (z2 + z3);
        lsq[o]  = (z0 * z0 + z1 * z1) + (z2 * z2 + z3 * z3);
    }

#pragma unroll
    for (int o = 0; o < 16; o++) {
#pragma unroll
        for (int s = 16; s > 0; s >>= 1) {
            lsum[o] += __shfl_xor_sync(0xffffffffu, lsum[o], s);
            lsq[o]  += __shfl_xor_sync(0xffffffffu, lsq[o],  s);
        }
    }
    const int w = t >> 5, lane = t & 31;
    if (lane == 0) {
#pragma unroll
        for (int o = 0; o < 16; o++) { sRed[w][o] = lsum[o]; sRed[w][16 + o] = lsq[o]; }
    }
    __syncthreads();
    if (t < 32) {
        float v = 0.f;
#pragma unroll
        for (int b = 0; b < 8; b++) v += sRed[b][t];
        int slice = (blockIdx.y * 12 + blockIdx.x) & 7;
        if (t < 16) atomicAdd(&g_sumP[slice][t], (double)v);
        else        atomicAdd(&g_sqP[slice][t - 16], (double)v);
    }
}

// ---------------------------------------------------------------------------
// Finalize BN affine; re-zero partials.  1 block, 32 threads.
// ---------------------------------------------------------------------------
__global__ void k_fin(const float* __restrict__ gamma, const float* __restrict__ beta,
                      int layer, int H) {
    __shared__ double ss[16], qq[16];
    int t = threadIdx.x;
    if (t < 16) {
        double s = 0.0, q = 0.0;
        for (int b = 0; b < 8; b++) { s += g_sumP[b][t]; q += g_sqP[b][t]; }
        ss[t] = s; qq[t] = q;
    }
    __syncthreads();
    for (int l = t; l < 128; l += 32) {
        ((double*)g_sumP)[l] = 0.0;
        ((double*)g_sqP)[l]  = 0.0;
    }
    if (t < H) {
        double mean = ss[t] / (double)NNSZ;
        double var  = qq[t] / (double)NNSZ - mean * mean;   // biased variance
        double inv  = 1.0 / sqrt(var + 1e-5);
        float  sc   = (float)((double)gamma[t] * inv);
        g_scaleA[layer][t] = sc;
        g_shiftA[layer][t] = beta[t] - (float)mean * sc;
    }
}

// ---------------------------------------------------------------------------
// Middle layer: BN(prev)+leaky on CI planes, matmul W[CO][CI]+bias, write CO
// planes, stats.  STRUCTURE = R6's proven no-spill shape (scalar h[16], 1
// position per loop iteration, regs=74) wrapped in a NON-UNROLLED 8-iteration
// grid-stride loop to amortize the SHFL reduction 8x.
// R8 (8x unroll, 128 live floats) and R9 (float4, 64 live floats) both made
// ptxas clamp to 32 regs and spill -> 3.7-4.6GB local traffic, ~790us.
// Live set here: h[16] per-iter + fsum/fsq[32] loop-carried ~= 74 regs.
// grid 1152 x 256thr x 8iter == NNSZ.
// ---------------------------------------------------------------------------
template <int CI, int CO>
__global__ void __launch_bounds__(256) k_mid(const float* __restrict__ Wm,
                                             const float* __restrict__ bias,
                                             int layerPrev) {
    __shared__ float sW[CO * CI];
    __shared__ float sS[CI], sH[CI], sB2[CO];
    __shared__ float sRed[8][32];
    int t = threadIdx.x;
    for (int l = t; l < CO * CI; l += 256) sW[l] = Wm[l];
    if (t < CI) { sS[t] = g_scaleA[layerPrev][t]; sH[t] = g_shiftA[layerPrev][t]; }
    if (t < CO) sB2[t] = bias[t];
    __syncthreads();

    float fsum[CO], fsq[CO];
#pragma unroll
    for (int o = 0; o < CO; o++) { fsum[o] = 0.f; fsq[o] = 0.f; }

    const int base = blockIdx.x * 2048 + t;
#pragma unroll 1
    for (int it = 0; it < 8; it++) {
        const int p = base + it * 256;
        float h[CI];
#pragma unroll
        for (int c = 0; c < CI; c++) {
            float z = g_z[c * NNSZ + p];
            z = z * sS[c] + sH[c];
            h[c] = (z >= 0.f) ? z : 0.01f * z;
        }
#pragma unroll
        for (int o = 0; o < CO; o++) {
            float a = sB2[o];
#pragma unroll
            for (int c = 0; c < CI; c++) a += sW[o * CI + c] * h[c];
            g_z[o * NNSZ + p] = a;
            fsum[o] += a;
            fsq[o]  += a * a;
        }
    }

#pragma unroll
    for (int o = 0; o < CO; o++) {
#pragma unroll
        for (int s = 16; s > 0; s >>= 1) {
            fsum[o] += __shfl_xor_sync(0xffffffffu, fsum[o], s);
            fsq[o]  += __shfl_xor_sync(0xffffffffu, fsq[o],  s);
        }
    }
    int w = t >> 5, lane = t & 31;
    if (lane == 0) {
#pragma unroll
        for (int o = 0; o < CO; o++) { sRed[w][o] = fsum[o]; sRed[w][CO + o] = fsq[o]; }
    }
    __syncthreads();
    if (t < 2 * CO) {
        float v = 0.f;
#pragma unroll
        for (int b = 0; b < 8; b++) v += sRed[b][t];
        int slice = blockIdx.x & 7;
        if (t < CO) atomicAdd(&g_sumP[slice][t], (double)v);
        else        atomicAdd(&g_sqP[slice][t - CO], (double)v);
    }
}

// ---------------------------------------------------------------------------
// Output: BN4 + leaky + dot with W5[8] + b5.  float4 x 4 iters (8 channels ->
// 32 live floats transient, no loop-carried arrays -> low pressure).
// ---------------------------------------------------------------------------
__global__ void __launch_bounds__(256) k_out(const float* __restrict__ W5,
                                             const float* __restrict__ b5,
                                             float* __restrict__ out) {
    __shared__ float sS[8], sH[8], sW[8];
    __shared__ float sb;
    int t = threadIdx.x;
    if (t < 8) { sS[t] = g_scaleA[3][t]; sH[t] = g_shiftA[3][t]; sW[t] = W5[t]; }
    if (t == 0) sb = b5[0];
    __syncthreads();
    const int base = blockIdx.x * 4096 + t * 4;
#pragma unroll 1
    for (int it = 0; it < 4; it++) {
        const int p = base + it * 1024;
        float4 a = make_float4(sb, sb, sb, sb);
#pragma unroll
        for (int c = 0; c < 8; c++) {
            float4 z = *(const float4*)&g_z[c * NNSZ + p];
            float sc = sS[c], sh = sH[c], w = sW[c];
            float h;
            h = z.x * sc + sh; h = (h >= 0.f) ? h : 0.01f * h; a.x += w * h;
            h = z.y * sc + sh; h = (h >= 0.f) ? h : 0.01f * h; a.y += w * h;
            h = z.z * sc + sh; h = (h >= 0.f) ? h : 0.01f * h; a.z += w * h;
            h = z.w * sc + sh; h = (h >= 0.f) ? h : 0.01f * h; a.w += w * h;
        }
        *(float4*)&out[p] = a;
    }
}

// ---------------------------------------------------------------------------
// Launch: 10 kernels, graph-capturable, allocation-free, no syncs.
// ---------------------------------------------------------------------------
extern "C" void kernel_launch(void* const* d_in, const int* in_sizes, int n_in,
                              void* d_out, int out_size) {
    (void)in_sizes; (void)n_in; (void)out_size;
    const float* x   = (const float*)d_in[0];
    const float* W1  = (const float*)d_in[1];
    const float* b1  = (const float*)d_in[2];
    const float* g1  = (const float*)d_in[3];
    const float* be1 = (const float*)d_in[4];
    const float* W2  = (const float*)d_in[5];
    const float* b2  = (const float*)d_in[6];
    const float* g2  = (const float*)d_in[7];
    const float* be2 = (const float*)d_in[8];
    const float* W3  = (const float*)d_in[9];
    const float* b3  = (const float*)d_in[10];
    const float* g3  = (const float*)d_in[11];
    const float* be3 = (const float*)d_in[12];
    const float* W4  = (const float*)d_in[13];
    const float* b4  = (const float*)d_in[14];
    const float* g4  = (const float*)d_in[15];
    const float* be4 = (const float*)d_in[16];
    const float* W5  = (const float*)d_in[17];
    const float* b5  = (const float*)d_in[18];
    float* out = (float*)d_out;

    k_zero<<<1, 128>>>();
    k_l1<<<dim3(NSZ / 128, NSZ / 8), 256>>>(x, W1, b1);        // z1 + stats1
    k_fin<<<1, 32>>>(g1, be1, 0, 16);
    k_mid<16, 16><<<NNSZ / 2048, 256>>>(W2, b2, 0);            // z2 + stats2
    k_fin<<<1, 32>>>(g2, be2, 1, 16);
    k_mid<16, 8><<<NNSZ / 2048, 256>>>(W3, b3, 1);             // z3 + stats3
    k_fin<<<1, 32>>>(g3, be3, 2, 8);
    k_mid<8, 8><<<NNSZ / 2048, 256>>>(W4, b4, 2);              // z4 + stats4
    k_fin<<<1, 32>>>(g4, be4, 3, 8);
    k_out<<<NNSZ / 4096, 256>>>(W5, b5, out);
}